// round 16
// baseline (speedup 1.0000x reference)
#include <cuda_runtime.h>
#include <cuda_fp16.h>
#include <cstdint>

// Problem constants
#define B_  16
#define S_  2048
#define D_  768
#define G_  1024
#define M_  (B_ * G_)          // 16384 rows (groups)

// GEMM tiling (mma.sync path; tcgen05 unavailable: harness targets sm_103 base)
#define MT   128
#define NT   128
#define KC   64
#define KCH  (D_ / KC)         // 12
#define NTM  (M_ / MT)         // 128
#define NTN  (D_ / NT)         // 6

#define ROWB        144                       // 64 fp16 = 128B data + 16B pad
#define A_TILE      (128 * ROWB)              // 18432
#define B_TILE      (128 * ROWB)              // 18432
#define STAGE_BYTES (A_TILE + B_TILE)         // 36864
#define NSTAGE      3
#define SMEM_BYTES  (NSTAGE * STAGE_BYTES)    // 110592 -> 2 CTAs/SM

#define PREPB_BLOCKS ((D_ * 96) / 256)        // 288
#define MASK_CTAS    6                        // grid row y == NTM
#define NFLAG        (NTM * NTN)              // 768 per-slice flags

// Prebuilt fp16 operand images (row-major)
__device__ __align__(16) __half gA[(size_t)M_ * D_];   // fp16(pair-mean)
__device__ __align__(16) __half gB[(size_t)D_ * D_];   // fp16(Wt[n][k])

// Cross-CTA sync state; a_flag + counters reset by prepB (prior launch),
// g_done self-resets.
__device__ int      a_flag[NFLAG];            // slice (y*6+s) ready
__device__ int      g_num_cnt;
__device__ int      g_den_cnt;
__device__ unsigned g_done = 0;

// ---------------------------------------------------------------------------
// helpers
// ---------------------------------------------------------------------------
__device__ __forceinline__ uint32_t smem_u32(const void* p) {
    uint32_t a;
    asm("{ .reg .u64 t; cvta.to.shared.u64 t, %1; cvt.u32.u64 %0, t; }" : "=r"(a) : "l"(p));
    return a;
}
__device__ __forceinline__ void cp16(uint32_t s, const void* g) {
    asm volatile("cp.async.cg.shared.global [%0], [%1], 16;" :: "r"(s), "l"(g));
}
__device__ __forceinline__ void cp_commit() {
    asm volatile("cp.async.commit_group;" ::: "memory");
}
__device__ __forceinline__ void ldm_x4(uint32_t* r, uint32_t addr) {
    asm volatile("ldmatrix.sync.aligned.m8n8.x4.shared.b16 {%0,%1,%2,%3}, [%4];"
                 : "=r"(r[0]), "=r"(r[1]), "=r"(r[2]), "=r"(r[3]) : "r"(addr));
}
__device__ __forceinline__ void mma_f16(float* c, const uint32_t* a, const uint32_t* b) {
    asm volatile(
        "mma.sync.aligned.m16n8k16.row.col.f32.f16.f16.f32 "
        "{%0,%1,%2,%3}, {%4,%5,%6,%7}, {%8,%9}, {%0,%1,%2,%3};"
        : "+f"(c[0]), "+f"(c[1]), "+f"(c[2]), "+f"(c[3])
        : "r"(a[0]), "r"(a[1]), "r"(a[2]), "r"(a[3]), "r"(b[0]), "r"(b[1]));
}
__device__ __forceinline__ uint32_t pack_h2(float a, float b) {
    __half2 h = __floats2half2_rn(a, b);
    return *reinterpret_cast<uint32_t*>(&h);
}
__device__ __forceinline__ float fast_tanh(float x) {
    float e = __expf(2.0f * x);
    return 1.0f - __fdividef(2.0f, e + 1.0f);
}

// ---------------------------------------------------------------------------
// Launch 1 (tiny): B = fp16(Wt); resets a_flag + counters for this replay.
// ---------------------------------------------------------------------------
__global__ __launch_bounds__(256)
void prepB_kernel(const float* __restrict__ W) {
    const int bid = blockIdx.x, tid = threadIdx.x;
    if (bid < 3) a_flag[bid * 256 + tid] = 0;
    if (bid == 0 && tid == 0) { g_num_cnt = 0; g_den_cnt = 0; }
    int g = bid * 256 + tid;                // < D_ * 96
    int n = g / 96, kg = g % 96;
    int k = kg * 8;
    uint32_t h[4];
    #pragma unroll
    for (int i = 0; i < 4; i++) {
        float f0 = W[(size_t)(k + 2*i)     * D_ + n];
        float f1 = W[(size_t)(k + 2*i + 1) * D_ + n];
        h[i] = pack_h2(f0, f1);
    }
    *reinterpret_cast<uint4*>(gB + (size_t)n * D_ + k) = make_uint4(h[0], h[1], h[2], h[3]);
}

// ---------------------------------------------------------------------------
// Launch 2: grid (6, 129).
//  y < 128 : CTA preps A-slice (rows of mtile y, k in [128x,128x+128)) ->
//            per-slice flag -> GEMM waiting per-slice just-in-time.
//  y == 128: masks + counters + compression_rate.
// ---------------------------------------------------------------------------
__global__ __launch_bounds__(256, 2)
void gemm_fused_kernel(const float* __restrict__ X, const float* __restrict__ bias,
                       const int* __restrict__ pad, const int* __restrict__ reg,
                       const int* __restrict__ seq, float* __restrict__ out)
{
    const int tid = threadIdx.x;
    const int xb  = blockIdx.x;              // 0..5
    const int yb  = blockIdx.y;              // 0..128
    const size_t NC = (size_t)M_ * D_;

    if (yb == NTM) {
        // ---- masks path (6 CTAs, dispatched last) ----
        int lnum = 0, lden = 0;
        for (int m = xb * 256 + tid; m < M_; m += MASK_CTAS * 256) {
            const int t0 = 2 * m, t1 = 2 * m + 1;
            const int p0 = pad[t0], p1 = pad[t1];
            const int r0 = reg[t0], r1 = reg[t1];
            const int s0 = seq[t0], s1 = seq[t1];
            const int mp = ((p0 + p1) != 0) ? 1 : 0;
            const int mr = ((r0 + r1) != 0) ? 1 : 0;
            int ms = ((s0 > 0) && (s1 > 0)) ? 1 : 0;
            if (mp == 0) ms = -1;
            out[NC + m]          = (float)mp;
            out[NC + M_ + m]     = (float)mr;
            out[NC + 2 * M_ + m] = (float)ms;
            lnum += mr;
            lden += r0 + r1;
        }
        unsigned num = __reduce_add_sync(0xffffffffu, (unsigned)lnum);
        unsigned den = __reduce_add_sync(0xffffffffu, (unsigned)lden);
        if ((tid & 31) == 0) {
            atomicAdd(&g_num_cnt, (int)num);
            atomicAdd(&g_den_cnt, (int)den);
        }
        __syncthreads();
        if (tid == 0) {
            __threadfence();
            unsigned t = atomicAdd(&g_done, 1u);
            if (t == MASK_CTAS - 1) {
                int nn = atomicAdd(&g_num_cnt, 0);
                int dd = atomicAdd(&g_den_cnt, 0);
                out[NC + 3 * M_] = (float)nn / (float)dd;
                g_done = 0;
            }
        }
        return;
    }

    // ---- A prep: this CTA owns slice xb of mtile yb (chunks 2xb, 2xb+1) ----
    {
        #pragma unroll
        for (int i = 0; i < 8; i++) {
            int u  = i * 256 + tid;          // 0..2047 (128 rows x 16 kgroups)
            int mr = u >> 4;
            int kg = u & 15;
            int m  = yb * MT + mr;
            int k  = xb * 128 + kg * 8;
            const float4* x0 = reinterpret_cast<const float4*>(X + (size_t)(2 * m) * D_ + k);
            const float4* x1 = reinterpret_cast<const float4*>(X + (size_t)(2 * m + 1) * D_ + k);
            float4 a0 = x0[0], a1 = x0[1], b0 = x1[0], b1 = x1[1];
            uint32_t h[4];
            h[0] = pack_h2(0.5f*(a0.x+b0.x), 0.5f*(a0.y+b0.y));
            h[1] = pack_h2(0.5f*(a0.z+b0.z), 0.5f*(a0.w+b0.w));
            h[2] = pack_h2(0.5f*(a1.x+b1.x), 0.5f*(a1.y+b1.y));
            h[3] = pack_h2(0.5f*(a1.z+b1.z), 0.5f*(a1.w+b1.w));
            *reinterpret_cast<uint4*>(gA + (size_t)m * D_ + k) = make_uint4(h[0], h[1], h[2], h[3]);
        }
    }
    __syncthreads();
    if (tid == 0) { __threadfence(); atomicExch(&a_flag[yb * NTN + xb], 1); }

    // spin (tid 0) until slice s of this row is published; caller syncs after.
    auto spin_slice = [&](int s) {
        if (s == xb) return;                  // self-produced
        if (tid == 0) {
            volatile int* f = a_flag;
            while (f[yb * NTN + s] == 0) __nanosleep(32);
        }
    };

    // ---- GEMM (round-12 loop + just-in-time slice gating) ----
    extern __shared__ unsigned char smem_dyn[];
    const uint32_t base = smem_u32(smem_dyn);
    const int wid  = tid >> 5, lane = tid & 31;
    const int m0   = yb * MT;
    const int n0   = xb * NT;
    const int wm   = (wid & 1) * 64;
    const int wn   = (wid >> 1) * 32;

    const unsigned char* pa = (const unsigned char*)(gA + (size_t)m0 * D_);
    const unsigned char* pb = (const unsigned char*)(gB + (size_t)n0 * D_);

    auto load_chunk = [&](int c, int s) {
        uint32_t st = base + s * STAGE_BYTES;
        #pragma unroll
        for (int i = 0; i < 4; i++) {
            int idx = tid + i * 256;
            int row = idx >> 3, j = idx & 7;
            size_t g = (size_t)row * (D_ * 2) + (size_t)c * (KC * 2) + j * 16;
            cp16(st + row * ROWB + j * 16,          pa + g);
            cp16(st + A_TILE + row * ROWB + j * 16, pb + g);
        }
        cp_commit();
    };

    float acc[4][4][4];
    #pragma unroll
    for (int i = 0; i < 4; i++)
        #pragma unroll
        for (int j = 0; j < 4; j++)
            #pragma unroll
            for (int q = 0; q < 4; q++) acc[i][j][q] = 0.0f;

    const uint32_t aByte = (uint32_t)((wm + (lane & 15)) * ROWB + (lane >> 4) * 16);
    const uint32_t bByte = (uint32_t)((wn + (lane & 7) + ((lane >> 4) & 1) * 8) * ROWB +
                                      ((lane >> 3) & 1) * 16);

    uint32_t AH[2][4][4];

    auto ldA = [&](int kk, int b, uint32_t sa) {
        const uint32_t ao = aByte + kk * 32;
        #pragma unroll
        for (int t = 0; t < 4; t++)
            ldm_x4(AH[b][t], sa + ao + t * (16 * ROWB));
    };

    // prologue: chunks 0,1 need slice 0
    spin_slice(0);
    __syncthreads();
    load_chunk(0, 0);
    load_chunk(1, 1);

    for (int c = 0; c < KCH; c++) {
        const int tgt = c + 2;
        // gate the upcoming prefetch on its slice flag (spin merges into the
        // single per-chunk barrier below)
        if (tgt < KCH && (tgt & 1) == 0) spin_slice(tgt >> 1);

        if (c < KCH - 1) asm volatile("cp.async.wait_group 1;" ::: "memory");
        else             asm volatile("cp.async.wait_group 0;" ::: "memory");
        __syncthreads();

        if (tgt < KCH) load_chunk(tgt, tgt % 3);

        const uint32_t st = base + (c % 3) * STAGE_BYTES;
        const uint32_t sa = st;
        const uint32_t sb = st + A_TILE;

        ldA(0, 0, sa);
        #pragma unroll
        for (int kk = 0; kk < 4; kk++) {
            const int b = kk & 1;
            const uint32_t bo = bByte + kk * 32;
            uint32_t BH[2][4];
            ldm_x4(BH[0], sb + bo);
            ldm_x4(BH[1], sb + bo + 16 * ROWB);
            if (kk < 3) ldA(kk + 1, b ^ 1, sa);
            #pragma unroll
            for (int u = 0; u < 2; u++) {
                #pragma unroll
                for (int i = 0; i < 4; i++) {
                    mma_f16(acc[i][2*u],   AH[b][i], BH[u]);
                    mma_f16(acc[i][2*u+1], AH[b][i], BH[u] + 2);
                }
            }
        }
    }

    // Epilogue: + bias, fast tanh, store
    const int mrow = m0 + wm + (lane >> 2);
    const int ncol = n0 + wn + (lane & 3) * 2;
    float bv[4][2];
    #pragma unroll
    for (int j = 0; j < 4; j++) {
        bv[j][0] = __ldg(bias + ncol + j * 8);
        bv[j][1] = __ldg(bias + ncol + j * 8 + 1);
    }
    #pragma unroll
    for (int i = 0; i < 4; i++) {
        const int r0 = mrow + i * 16;
        #pragma unroll
        for (int j = 0; j < 4; j++) {
            const int col = ncol + j * 8;
            float2 v0, v1;
            v0.x = fast_tanh(acc[i][j][0] + bv[j][0]);
            v0.y = fast_tanh(acc[i][j][1] + bv[j][1]);
            v1.x = fast_tanh(acc[i][j][2] + bv[j][0]);
            v1.y = fast_tanh(acc[i][j][3] + bv[j][1]);
            *reinterpret_cast<float2*>(out + (size_t)r0 * D_ + col)       = v0;
            *reinterpret_cast<float2*>(out + (size_t)(r0 + 8) * D_ + col) = v1;
        }
    }
}

// ---------------------------------------------------------------------------
extern "C" void kernel_launch(void* const* d_in, const int* in_sizes, int n_in,
                              void* d_out, int out_size)
{
    const float* X    = (const float*)d_in[0];
    const int*   pad  = (const int*)d_in[2];
    const int*   reg  = (const int*)d_in[3];
    const int*   seq  = (const int*)d_in[4];
    const float* W    = (const float*)d_in[6];
    const float* bias = (const float*)d_in[7];
    float*       out  = (float*)d_out;

    cudaFuncSetAttribute(gemm_fused_kernel,
                         cudaFuncAttributeMaxDynamicSharedMemorySize, SMEM_BYTES);

    prepB_kernel<<<PREPB_BLOCKS, 256>>>(W);
    gemm_fused_kernel<<<dim3(NTN, NTM + 1), 256, SMEM_BYTES>>>(X, bias, pad, reg, seq, out);
}

// round 17
// speedup vs baseline: 1.1547x; 1.1547x over previous
#include <cuda_runtime.h>
#include <cuda_fp16.h>
#include <cstdint>

// Problem constants
#define B_  16
#define S_  2048
#define D_  768
#define G_  1024
#define M_  (B_ * G_)          // 16384 rows (groups)

// GEMM tiling (mma.sync path; tcgen05 unavailable: harness targets sm_103 base)
#define MT   128
#define NT   128
#define KC   64
#define KCH  (D_ / KC)         // 12
#define NTM  (M_ / MT)         // 128
#define NTN  (D_ / NT)         // 6

#define ROWB        144                       // 64 fp16 = 128B data + 16B pad
#define A_TILE      (128 * ROWB)              // 18432
#define B_TILE      (128 * ROWB)              // 18432
#define STAGE_BYTES (A_TILE + B_TILE)         // 36864
#define NSTAGE      3
#define SMEM_BYTES  (NSTAGE * STAGE_BYTES)    // 110592 -> 2 CTAs/SM

#define PREPB_BLOCKS ((D_ * 96) / 256)        // 288
#define PREPA_BLOCKS ((M_ * 96) / 256)        // 6144
#define PREP_GRID    (PREPB_BLOCKS + PREPA_BLOCKS)
#define MASK_CTAS    6                        // grid row y == NTM of GEMM launch

// Prebuilt fp16 operand images (row-major)
__device__ __align__(16) __half gA[(size_t)M_ * D_];   // fp16(pair-mean)
__device__ __align__(16) __half gB[(size_t)D_ * D_];   // fp16(Wt[n][k])

__device__ int      g_num_cnt;   // reset by prep launch each replay
__device__ int      g_den_cnt;
__device__ unsigned g_done = 0;  // self-resets in mask finalizer

// ---------------------------------------------------------------------------
// helpers
// ---------------------------------------------------------------------------
__device__ __forceinline__ uint32_t smem_u32(const void* p) {
    uint32_t a;
    asm("{ .reg .u64 t; cvta.to.shared.u64 t, %1; cvt.u32.u64 %0, t; }" : "=r"(a) : "l"(p));
    return a;
}
__device__ __forceinline__ void cp16(uint32_t s, const void* g) {
    asm volatile("cp.async.cg.shared.global [%0], [%1], 16;" :: "r"(s), "l"(g));
}
__device__ __forceinline__ void cp_commit() {
    asm volatile("cp.async.commit_group;" ::: "memory");
}
__device__ __forceinline__ void ldm_x4(uint32_t* r, uint32_t addr) {
    asm volatile("ldmatrix.sync.aligned.m8n8.x4.shared.b16 {%0,%1,%2,%3}, [%4];"
                 : "=r"(r[0]), "=r"(r[1]), "=r"(r[2]), "=r"(r[3]) : "r"(addr));
}
__device__ __forceinline__ void mma_f16(float* c, const uint32_t* a, const uint32_t* b) {
    asm volatile(
        "mma.sync.aligned.m16n8k16.row.col.f32.f16.f16.f32 "
        "{%0,%1,%2,%3}, {%4,%5,%6,%7}, {%8,%9}, {%0,%1,%2,%3};"
        : "+f"(c[0]), "+f"(c[1]), "+f"(c[2]), "+f"(c[3])
        : "r"(a[0]), "r"(a[1]), "r"(a[2]), "r"(a[3]), "r"(b[0]), "r"(b[1]));
}
__device__ __forceinline__ uint32_t pack_h2(float a, float b) {
    __half2 h = __floats2half2_rn(a, b);
    return *reinterpret_cast<uint32_t*>(&h);
}
// evict-first streaming load of 16B (X is single-use; keep L2 for gA/gB)
__device__ __forceinline__ float4 ldcs4(const float4* p) {
    float4 v;
    asm volatile("ld.global.cs.v4.f32 {%0,%1,%2,%3}, [%4];"
                 : "=f"(v.x), "=f"(v.y), "=f"(v.z), "=f"(v.w) : "l"(p));
    return v;
}
// tanh via exp: ~1e-6 rel err, exact saturation.
__device__ __forceinline__ float fast_tanh(float x) {
    float e = __expf(2.0f * x);
    return 1.0f - __fdividef(2.0f, e + 1.0f);
}

// ---------------------------------------------------------------------------
// Launch 1: prep (B then A; no masks). Resets counters for this replay.
// ---------------------------------------------------------------------------
__global__ __launch_bounds__(256)
void prep_all_kernel(const float* __restrict__ X, const float* __restrict__ W) {
    const int bid = blockIdx.x;
    const int tid = threadIdx.x;
    if (bid < PREPB_BLOCKS) {
        if (bid == 0 && tid == 0) { g_num_cnt = 0; g_den_cnt = 0; }
        int g = bid * 256 + tid;                // < D_ * 96
        int n = g / 96, kg = g % 96;
        int k = kg * 8;
        uint32_t h[4];
        #pragma unroll
        for (int i = 0; i < 4; i++) {
            float f0 = W[(size_t)(k + 2*i)     * D_ + n];
            float f1 = W[(size_t)(k + 2*i + 1) * D_ + n];
            h[i] = pack_h2(f0, f1);
        }
        *reinterpret_cast<uint4*>(gB + (size_t)n * D_ + k) = make_uint4(h[0], h[1], h[2], h[3]);
    } else {
        int g = (bid - PREPB_BLOCKS) * 256 + tid;   // < M_ * 96
        int m = g / 96, kg = g % 96;
        int k = kg * 8;
        const float4* x0 = reinterpret_cast<const float4*>(X + (size_t)(2 * m) * D_ + k);
        const float4* x1 = reinterpret_cast<const float4*>(X + (size_t)(2 * m + 1) * D_ + k);
        float4 a0 = ldcs4(x0),     a1 = ldcs4(x0 + 1);
        float4 b0 = ldcs4(x1),     b1 = ldcs4(x1 + 1);
        uint32_t h[4];
        h[0] = pack_h2(0.5f*(a0.x+b0.x), 0.5f*(a0.y+b0.y));
        h[1] = pack_h2(0.5f*(a0.z+b0.z), 0.5f*(a0.w+b0.w));
        h[2] = pack_h2(0.5f*(a1.x+b1.x), 0.5f*(a1.y+b1.y));
        h[3] = pack_h2(0.5f*(a1.z+b1.z), 0.5f*(a1.w+b1.w));
        *reinterpret_cast<uint4*>(gA + (size_t)m * D_ + k) = make_uint4(h[0], h[1], h[2], h[3]);
    }
}

// ---------------------------------------------------------------------------
// Launch 2: grid (6, 129).
//  y < 128 : GEMM C = tanh(A@W + b) — round-12 loop (3-stage cp.async,
//            A-fragments double-buffered, 1 barrier per chunk).
//  y == 128: masks + counters + compression_rate (6 CTAs, tail shadow).
// ---------------------------------------------------------------------------
__global__ __launch_bounds__(256, 2)
void gemm_fused_kernel(const float* __restrict__ bias,
                       const int* __restrict__ pad, const int* __restrict__ reg,
                       const int* __restrict__ seq, float* __restrict__ out)
{
    const int tid = threadIdx.x;
    const int xb  = blockIdx.x;              // 0..5
    const int yb  = blockIdx.y;              // 0..128
    const size_t NC = (size_t)M_ * D_;

    if (yb == NTM) {
        // ---- masks path ----
        int lnum = 0, lden = 0;
        for (int m = xb * 256 + tid; m < M_; m += MASK_CTAS * 256) {
            const int t0 = 2 * m, t1 = 2 * m + 1;
            const int p0 = pad[t0], p1 = pad[t1];
            const int r0 = reg[t0], r1 = reg[t1];
            const int s0 = seq[t0], s1 = seq[t1];
            const int mp = ((p0 + p1) != 0) ? 1 : 0;
            const int mr = ((r0 + r1) != 0) ? 1 : 0;
            int ms = ((s0 > 0) && (s1 > 0)) ? 1 : 0;
            if (mp == 0) ms = -1;
            out[NC + m]          = (float)mp;
            out[NC + M_ + m]     = (float)mr;
            out[NC + 2 * M_ + m] = (float)ms;
            lnum += mr;
            lden += r0 + r1;
        }
        unsigned num = __reduce_add_sync(0xffffffffu, (unsigned)lnum);
        unsigned den = __reduce_add_sync(0xffffffffu, (unsigned)lden);
        if ((tid & 31) == 0) {
            atomicAdd(&g_num_cnt, (int)num);
            atomicAdd(&g_den_cnt, (int)den);
        }
        __syncthreads();
        if (tid == 0) {
            __threadfence();
            unsigned t = atomicAdd(&g_done, 1u);
            if (t == MASK_CTAS - 1) {
                int nn = atomicAdd(&g_num_cnt, 0);
                int dd = atomicAdd(&g_den_cnt, 0);
                out[NC + 3 * M_] = (float)nn / (float)dd;
                g_done = 0;   // self-reset for next replay
            }
        }
        return;
    }

    // ---- GEMM path ----
    extern __shared__ unsigned char smem_dyn[];
    const uint32_t base = smem_u32(smem_dyn);
    const int wid  = tid >> 5, lane = tid & 31;
    const int m0   = yb * MT;
    const int n0   = xb * NT;
    const int wm   = (wid & 1) * 64;
    const int wn   = (wid >> 1) * 32;

    const unsigned char* pa = (const unsigned char*)(gA + (size_t)m0 * D_);
    const unsigned char* pb = (const unsigned char*)(gB + (size_t)n0 * D_);

    auto load_chunk = [&](int c, int s) {
        uint32_t st = base + s * STAGE_BYTES;
        #pragma unroll
        for (int i = 0; i < 4; i++) {
            int idx = tid + i * 256;
            int row = idx >> 3, j = idx & 7;
            size_t g = (size_t)row * (D_ * 2) + (size_t)c * (KC * 2) + j * 16;
            cp16(st + row * ROWB + j * 16,          pa + g);
            cp16(st + A_TILE + row * ROWB + j * 16, pb + g);
        }
        cp_commit();
    };

    float acc[4][4][4];
    #pragma unroll
    for (int i = 0; i < 4; i++)
        #pragma unroll
        for (int j = 0; j < 4; j++)
            #pragma unroll
            for (int q = 0; q < 4; q++) acc[i][j][q] = 0.0f;

    const uint32_t aByte = (uint32_t)((wm + (lane & 15)) * ROWB + (lane >> 4) * 16);
    const uint32_t bByte = (uint32_t)((wn + (lane & 7) + ((lane >> 4) & 1) * 8) * ROWB +
                                      ((lane >> 3) & 1) * 16);

    uint32_t AH[2][4][4];

    auto ldA = [&](int kk, int b, uint32_t sa) {
        const uint32_t ao = aByte + kk * 32;
        #pragma unroll
        for (int t = 0; t < 4; t++)
            ldm_x4(AH[b][t], sa + ao + t * (16 * ROWB));
    };

    load_chunk(0, 0);
    load_chunk(1, 1);

    for (int c = 0; c < KCH; c++) {
        if (c < KCH - 1) asm volatile("cp.async.wait_group 1;" ::: "memory");
        else             asm volatile("cp.async.wait_group 0;" ::: "memory");
        __syncthreads();

        if (c + 2 < KCH) load_chunk(c + 2, (c + 2) % 3);

        const uint32_t st = base + (c % 3) * STAGE_BYTES;
        const uint32_t sa = st;
        const uint32_t sb = st + A_TILE;

        ldA(0, 0, sa);
        #pragma unroll
        for (int kk = 0; kk < 4; kk++) {
            const int b = kk & 1;
            const uint32_t bo = bByte + kk * 32;
            uint32_t BH[2][4];
            ldm_x4(BH[0], sb + bo);
            ldm_x4(BH[1], sb + bo + 16 * ROWB);
            if (kk < 3) ldA(kk + 1, b ^ 1, sa);
            #pragma unroll
            for (int u = 0; u < 2; u++) {
                #pragma unroll
                for (int i = 0; i < 4; i++) {
                    mma_f16(acc[i][2*u],   AH[b][i], BH[u]);
                    mma_f16(acc[i][2*u+1], AH[b][i], BH[u] + 2);
                }
            }
        }
    }

    // Epilogue: + bias, fast tanh, store
    const int mrow = m0 + wm + (lane >> 2);
    const int ncol = n0 + wn + (lane & 3) * 2;
    float bv[4][2];
    #pragma unroll
    for (int j = 0; j < 4; j++) {
        bv[j][0] = __ldg(bias + ncol + j * 8);
        bv[j][1] = __ldg(bias + ncol + j * 8 + 1);
    }
    #pragma unroll
    for (int i = 0; i < 4; i++) {
        const int r0 = mrow + i * 16;
        #pragma unroll
        for (int j = 0; j < 4; j++) {
            const int col = ncol + j * 8;
            float2 v0, v1;
            v0.x = fast_tanh(acc[i][j][0] + bv[j][0]);
            v0.y = fast_tanh(acc[i][j][1] + bv[j][1]);
            v1.x = fast_tanh(acc[i][j][2] + bv[j][0]);
            v1.y = fast_tanh(acc[i][j][3] + bv[j][1]);
            *reinterpret_cast<float2*>(out + (size_t)r0 * D_ + col)       = v0;
            *reinterpret_cast<float2*>(out + (size_t)(r0 + 8) * D_ + col) = v1;
        }
    }
}

// ---------------------------------------------------------------------------
extern "C" void kernel_launch(void* const* d_in, const int* in_sizes, int n_in,
                              void* d_out, int out_size)
{
    const float* X    = (const float*)d_in[0];
    const int*   pad  = (const int*)d_in[2];
    const int*   reg  = (const int*)d_in[3];
    const int*   seq  = (const int*)d_in[4];
    const float* W    = (const float*)d_in[6];
    const float* bias = (const float*)d_in[7];
    float*       out  = (float*)d_out;

    cudaFuncSetAttribute(gemm_fused_kernel,
                         cudaFuncAttributeMaxDynamicSharedMemorySize, SMEM_BYTES);

    prep_all_kernel<<<PREP_GRID, 256>>>(X, W);
    gemm_fused_kernel<<<dim3(NTN, NTM + 1), 256, SMEM_BYTES>>>(bias, pad, reg, seq, out);
}